// round 9
// baseline (speedup 1.0000x reference)
#include <cuda_runtime.h>
#include <cuda_bf16.h>
#include <math.h>
#include <stdint.h>

#define B_   2
#define T_   2048
#define E_   2048
#define H_   16
#define KVW_ 512
#define NR_  (B_*T_)   // 4096 rows

// ---------------- scratch (static device globals; no allocation) ----------------
__device__ __align__(16) float g_q[(size_t)NR_ * E_];
__device__ __align__(16) float g_k[(size_t)NR_ * KVW_];
__device__ __align__(16) float g_v[(size_t)NR_ * KVW_];
__device__ __align__(16) float g_part[4][(size_t)NR_ * E_];   // per-member w*O/l
// bf16 split buffers
__device__ __align__(16) __nv_bfloat16 g_ah[(size_t)NR_ * E_];   // x, later normed
__device__ __align__(16) __nv_bfloat16 g_al[(size_t)NR_ * E_];
__device__ __align__(16) __nv_bfloat16 g_qh[(size_t)NR_ * E_];   // roped+scaled q
__device__ __align__(16) __nv_bfloat16 g_ql[(size_t)NR_ * E_];
__device__ __align__(16) __nv_bfloat16 g_kh[(size_t)NR_ * KVW_]; // roped k
__device__ __align__(16) __nv_bfloat16 g_kl[(size_t)NR_ * KVW_];
__device__ __align__(16) __nv_bfloat16 g_vh[(size_t)NR_ * KVW_];
__device__ __align__(16) __nv_bfloat16 g_vl[(size_t)NR_ * KVW_];
__device__ __align__(16) __nv_bfloat16 g_qwh[(size_t)E_ * E_];
__device__ __align__(16) __nv_bfloat16 g_qwl[(size_t)E_ * E_];
__device__ __align__(16) __nv_bfloat16 g_kwh[(size_t)KVW_ * E_];
__device__ __align__(16) __nv_bfloat16 g_kwl[(size_t)KVW_ * E_];
__device__ __align__(16) __nv_bfloat16 g_vwh[(size_t)KVW_ * E_];
__device__ __align__(16) __nv_bfloat16 g_vwl[(size_t)KVW_ * E_];
__device__ __align__(16) __nv_bfloat16 g_owh[(size_t)E_ * E_];
__device__ __align__(16) __nv_bfloat16 g_owl[(size_t)E_ * E_];

__device__ __forceinline__ uint32_t smem_u32(const void* p) {
    uint32_t a;
    asm("{ .reg .u64 t; cvta.to.shared.u64 t, %1; cvt.u32.u64 %0, t; }" : "=r"(a) : "l"(p));
    return a;
}
__device__ __forceinline__ void ldsm_x4(uint32_t* r, uint32_t addr) {
    asm volatile("ldmatrix.sync.aligned.m8n8.x4.shared.b16 {%0,%1,%2,%3}, [%4];"
        : "=r"(r[0]), "=r"(r[1]), "=r"(r[2]), "=r"(r[3]) : "r"(addr));
}
__device__ __forceinline__ void ldsm_x4t(uint32_t* r, uint32_t addr) {
    asm volatile("ldmatrix.sync.aligned.m8n8.x4.trans.shared.b16 {%0,%1,%2,%3}, [%4];"
        : "=r"(r[0]), "=r"(r[1]), "=r"(r[2]), "=r"(r[3]) : "r"(addr));
}
__device__ __forceinline__ void ldsm_x2(uint32_t* r, uint32_t addr) {
    asm volatile("ldmatrix.sync.aligned.m8n8.x2.shared.b16 {%0,%1}, [%2];"
        : "=r"(r[0]), "=r"(r[1]) : "r"(addr));
}
__device__ __forceinline__ void mma_bf16(float* d, const uint32_t* a, const uint32_t* b) {
    asm volatile("mma.sync.aligned.m16n8k16.row.col.f32.bf16.bf16.f32 "
        "{%0,%1,%2,%3}, {%4,%5,%6,%7}, {%8,%9}, {%0,%1,%2,%3};"
        : "+f"(d[0]), "+f"(d[1]), "+f"(d[2]), "+f"(d[3])
        : "r"(a[0]), "r"(a[1]), "r"(a[2]), "r"(a[3]), "r"(b[0]), "r"(b[1]));
}
__device__ __forceinline__ void split_bf16(float v, __nv_bfloat16& h, __nv_bfloat16& l) {
    h = __float2bfloat16(v);
    l = __float2bfloat16(v - __bfloat162float(h));
}

// ---------------- fp32 -> (bf16 hi, bf16 lo) split ----------------
__global__ void cvt_split(const float4* __restrict__ in,
                          __nv_bfloat162* __restrict__ hi,
                          __nv_bfloat162* __restrict__ lo, int n4)
{
    int i = blockIdx.x * blockDim.x + threadIdx.x;
    if (i >= n4) return;
    float4 v = in[i];
    __nv_bfloat16 h0,h1,h2,h3,l0,l1,l2,l3;
    split_bf16(v.x,h0,l0); split_bf16(v.y,h1,l1);
    split_bf16(v.z,h2,l2); split_bf16(v.w,h3,l3);
    hi[i*2]   = __halves2bfloat162(h0, h1);
    hi[i*2+1] = __halves2bfloat162(h2, h3);
    lo[i*2]   = __halves2bfloat162(l0, l1);
    lo[i*2+1] = __halves2bfloat162(l2, l3);
}

// ---------------- fused RoPE + scale + split: fp32 buf -> bf16 hi/lo ----------------
__global__ void rope_split(const float* __restrict__ buf,
                           const float* __restrict__ cosb,
                           const float* __restrict__ sinb,
                           __nv_bfloat162* __restrict__ hi,
                           __nv_bfloat162* __restrict__ lo,
                           int nh, float scale)
{
    int idx = blockIdx.x * blockDim.x + threadIdx.x;
    int total = NR_ * nh * 16;
    if (idx >= total) return;
    int j    = idx & 15;
    int rest = idx >> 4;
    int head = rest % nh;
    int row  = rest / nh;
    int t    = row & (T_ - 1);
    float c = cosb[t*16 + j];
    float s = sinb[t*16 + j];
    const float* p = buf + (size_t)row * (nh*32) + head*32 + 2*j;
    float x1 = p[0], x2 = p[1];
    float o1 = (x1*c - x2*s) * scale;
    float o2 = (x1*s + x2*c) * scale;
    __nv_bfloat16 h1,l1,h2,l2;
    split_bf16(o1,h1,l1);
    split_bf16(o2,h2,l2);
    size_t oi = ((size_t)row * (nh*32) + head*32 + 2*j) >> 1;
    hi[oi] = __halves2bfloat162(h1, h2);
    lo[oi] = __halves2bfloat162(l1, l2);
}

// ---------------- HMMA GEMM: C[N,J] = A[N,K] @ W[J,K]^T, split-bf16 x3 ----------------
#define TSTRIDE 40
__global__ __launch_bounds__(256) void mma_gemm(
    const __nv_bfloat16* __restrict__ Ah, const __nv_bfloat16* __restrict__ Al,
    const __nv_bfloat16* __restrict__ Bh, const __nv_bfloat16* __restrict__ Bl,
    float* __restrict__ C, int J, int K)
{
    __shared__ __align__(16) __nv_bfloat16 sm[4][128 * TSTRIDE];

    const int tid  = threadIdx.x;
    const int lane = tid & 31;
    const int warp = tid >> 5;
    const int wr   = warp >> 2;
    const int wc   = warp & 3;
    const int bm   = blockIdx.y * 128;
    const int bn   = blockIdx.x * 128;

    const uint32_t sA_h = smem_u32(sm[0]);
    const uint32_t sA_l = smem_u32(sm[1]);
    const uint32_t sB_h = smem_u32(sm[2]);
    const uint32_t sB_l = smem_u32(sm[3]);

    const int K8 = K >> 3;
    const uint4* pAh = (const uint4*)Ah;
    const uint4* pAl = (const uint4*)Al;
    const uint4* pBh = (const uint4*)Bh;
    const uint4* pBl = (const uint4*)Bl;

    float d[4][4][4];
#pragma unroll
    for (int mi = 0; mi < 4; mi++)
#pragma unroll
        for (int ni = 0; ni < 4; ni++)
#pragma unroll
            for (int e = 0; e < 4; e++) d[mi][ni][e] = 0.f;

    const int a_row = lane & 15, a_coff = (lane >> 4) * 8;
    const int b_row = lane & 7,  b_coff = ((lane >> 3) & 1) * 8;

    const int nit = K >> 5;
#pragma unroll 1
    for (int it = 0; it < nit; it++) {
        const int k0u4 = it * 4;
        __syncthreads();
#pragma unroll
        for (int u = 0; u < 2; u++) {
            int c   = u * 256 + tid;
            int row = c >> 2, ch = c & 3;
            size_t ga = (size_t)(bm + row) * K8 + k0u4 + ch;
            size_t gb = (size_t)(bn + row) * K8 + k0u4 + ch;
            *(uint4*)((char*)sm[0] + row * (TSTRIDE*2) + ch * 16) = pAh[ga];
            *(uint4*)((char*)sm[1] + row * (TSTRIDE*2) + ch * 16) = pAl[ga];
            *(uint4*)((char*)sm[2] + row * (TSTRIDE*2) + ch * 16) = pBh[gb];
            *(uint4*)((char*)sm[3] + row * (TSTRIDE*2) + ch * 16) = pBl[gb];
        }
        __syncthreads();

#pragma unroll
        for (int kk = 0; kk < 32; kk += 16) {
            uint32_t ah[4][4], al[4][4], bh[4][2], bl[4][2];
#pragma unroll
            for (int mi = 0; mi < 4; mi++) {
                int row = wr*64 + mi*16 + a_row;
                uint32_t off = (uint32_t)(row * (TSTRIDE*2) + (kk + a_coff) * 2);
                ldsm_x4(ah[mi], sA_h + off);
                ldsm_x4(al[mi], sA_l + off);
            }
#pragma unroll
            for (int ni = 0; ni < 4; ni++) {
                int row = wc*32 + ni*8 + b_row;
                uint32_t off = (uint32_t)(row * (TSTRIDE*2) + (kk + b_coff) * 2);
                ldsm_x2(bh[ni], sB_h + off);
                ldsm_x2(bl[ni], sB_l + off);
            }
#pragma unroll
            for (int mi = 0; mi < 4; mi++)
#pragma unroll
                for (int ni = 0; ni < 4; ni++) {
                    mma_bf16(d[mi][ni], ah[mi], bh[ni]);
                    mma_bf16(d[mi][ni], ah[mi], bl[ni]);
                    mma_bf16(d[mi][ni], al[mi], bh[ni]);
                }
        }
    }

#pragma unroll
    for (int mi = 0; mi < 4; mi++) {
#pragma unroll
        for (int ni = 0; ni < 4; ni++) {
            int row = bm + wr*64 + mi*16 + (lane >> 2);
            int col = bn + wc*32 + ni*8 + (lane & 3)*2;
            *(float2*)&C[(size_t)row * J + col]       = make_float2(d[mi][ni][0], d[mi][ni][1]);
            *(float2*)&C[(size_t)(row + 8) * J + col] = make_float2(d[mi][ni][2], d[mi][ni][3]);
        }
    }
}

// ---------------- HMMA flash attention: one (q-tile, head, batch, member) per CTA ----------------
// smem layout (bytes): QH 0, QL 5120, KH 10240, KL 15360, VH 20480, VL 37888,
//                      PH 55296, PL 64512, stats 73728..75520
#define QS 40
#define VS 136
#define PS 72
#define ATTN_SMEM 75520
__global__ __launch_bounds__(256) void attn_mma(
    const __nv_bfloat16* __restrict__ qh, const __nv_bfloat16* __restrict__ ql,
    const __nv_bfloat16* __restrict__ kh, const __nv_bfloat16* __restrict__ kl,
    const __nv_bfloat16* __restrict__ vh, const __nv_bfloat16* __restrict__ vl,
    const float* __restrict__ rawm, const float* __restrict__ wsc,
    float* __restrict__ part)
{
    extern __shared__ char sm[];
    __nv_bfloat16* QH = (__nv_bfloat16*)(sm);
    __nv_bfloat16* QL = (__nv_bfloat16*)(sm + 5120);
    __nv_bfloat16* KH = (__nv_bfloat16*)(sm + 10240);
    __nv_bfloat16* KL = (__nv_bfloat16*)(sm + 15360);
    __nv_bfloat16* VH = (__nv_bfloat16*)(sm + 20480);
    __nv_bfloat16* VL = (__nv_bfloat16*)(sm + 37888);
    __nv_bfloat16* PH = (__nv_bfloat16*)(sm + 55296);
    __nv_bfloat16* PL = (__nv_bfloat16*)(sm + 64512);
    float* m_s  = (float*)(sm + 73728);
    float* l_s  = (float*)(sm + 73728 + 256);
    float* al_s = (float*)(sm + 73728 + 512);
    float* pmax = (float*)(sm + 73728 + 768);   // [2][64]
    float* psum = (float*)(sm + 73728 + 1280);  // [2][64]

    const int tid    = threadIdx.x;
    const int lane   = tid & 31;
    const int warp   = tid >> 5;
    const int rs     = (warp & 3) * 16;   // row strip
    const int cstrip = warp >> 2;         // 0/1
    const int qt  = (int)gridDim.x - 1 - (int)blockIdx.x;
    const int h   = blockIdx.y;
    const int bz  = blockIdx.z;
    const int b   = bz >> 2, mm = bz & 3;
    const int hkv = h >> 2;
    const int rowbase = b*T_ + qt*64;

    const uint32_t qh_b = smem_u32(QH), ql_b = smem_u32(QL);
    const uint32_t kh_b = smem_u32(KH), kl_b = smem_u32(KL);
    const uint32_t vh_b = smem_u32(VH), vl_b = smem_u32(VL);
    const uint32_t ph_b = smem_u32(PH), pl_b = smem_u32(PL);

    // load Q tile (pre-roped, pre-scaled, pre-split): 64x32 bf16 per plane
    {
        int r = tid >> 2, seg = tid & 3;
        size_t eo = (size_t)(rowbase + r)*E_ + (h*4 + mm)*32 + seg*8;
        *(uint4*)(QH + r*QS + seg*8) = *(const uint4*)(qh + eo);
        *(uint4*)(QL + r*QS + seg*8) = *(const uint4*)(ql + eo);
    }
    if (tid < 64) { m_s[tid] = -1e30f; l_s[tid] = 0.f; }

    float o[8][4];
#pragma unroll
    for (int n8 = 0; n8 < 8; n8++)
#pragma unroll
        for (int e = 0; e < 4; e++) o[n8][e] = 0.f;

    const int r0 = rs + (lane >> 2);
    const int r1 = r0 + 8;

#pragma unroll 1
    for (int kt = 0; kt <= qt; kt++) {
        const int kbase = b*T_ + kt*64;
        // stage K/V (bf16 pre-split)
        uint4 krh, krl, vrh[4], vrl[4];
        {
            int r = tid >> 2, seg = tid & 3;
            size_t eo = (size_t)(kbase + r)*KVW_ + (hkv*4 + mm)*32 + seg*8;
            krh = *(const uint4*)(kh + eo);
            krl = *(const uint4*)(kl + eo);
        }
#pragma unroll
        for (int u = 0; u < 4; u++) {
            int li = u*256 + tid;
            int kv = li >> 4, e8 = li & 15;
            size_t eo = (size_t)(kbase + kv)*KVW_ + hkv*128 + e8*8;
            vrh[u] = *(const uint4*)(vh + eo);
            vrl[u] = *(const uint4*)(vl + eo);
        }
        __syncthreads();   // prior MMA reads of K/V smem complete
        {
            int r = tid >> 2, seg = tid & 3;
            *(uint4*)(KH + r*QS + seg*8) = krh;
            *(uint4*)(KL + r*QS + seg*8) = krl;
        }
#pragma unroll
        for (int u = 0; u < 4; u++) {
            int li = u*256 + tid;
            int kv = li >> 4, e8 = li & 15;
            *(uint4*)(VH + kv*VS + e8*8) = vrh[u];
            *(uint4*)(VL + kv*VS + e8*8) = vrl[u];
        }
        __syncthreads();

        // S = Q K^T (64x64), warp tile 16x32 at (rs, cstrip*32)
        float s[4][4];
#pragma unroll
        for (int n8 = 0; n8 < 4; n8++)
#pragma unroll
            for (int e = 0; e < 4; e++) s[n8][e] = 0.f;
#pragma unroll
        for (int ks = 0; ks < 2; ks++) {
            int kk = ks*16;
            uint32_t aH[4], aL[4];
            uint32_t aoff = (uint32_t)(((rs + (lane & 15))*QS + kk + (lane >> 4)*8) * 2);
            ldsm_x4(aH, qh_b + aoff);
            ldsm_x4(aL, ql_b + aoff);
            uint32_t bH[2][4], bL[2][4];
#pragma unroll
            for (int np = 0; np < 2; np++) {
                int nrow = cstrip*32 + np*16 + (lane & 7) + 8*(lane >> 4);
                uint32_t boff = (uint32_t)((nrow*QS + kk + 8*((lane >> 3) & 1)) * 2);
                ldsm_x4(bH[np], kh_b + boff);
                ldsm_x4(bL[np], kl_b + boff);
            }
#pragma unroll
            for (int n8 = 0; n8 < 4; n8++) {
                uint32_t* bh = &bH[n8 >> 1][(n8 & 1)*2];
                uint32_t* bl = &bL[n8 >> 1][(n8 & 1)*2];
                mma_bf16(s[n8], aH, bh);
                mma_bf16(s[n8], aH, bl);
                mma_bf16(s[n8], aL, bh);
            }
        }
        // causal mask (diagonal tile only)
        if (kt == qt) {
#pragma unroll
            for (int n8 = 0; n8 < 4; n8++) {
                int c0 = cstrip*32 + n8*8 + (lane & 3)*2;
                if (c0     > r0) s[n8][0] = -1e30f;
                if (c0 + 1 > r0) s[n8][1] = -1e30f;
                if (c0     > r1) s[n8][2] = -1e30f;
                if (c0 + 1 > r1) s[n8][3] = -1e30f;
            }
        }
        // row max partials
        {
            float mx0 = s[0][0], mx1 = s[0][2];
#pragma unroll
            for (int n8 = 0; n8 < 4; n8++) {
                mx0 = fmaxf(mx0, fmaxf(s[n8][0], s[n8][1]));
                mx1 = fmaxf(mx1, fmaxf(s[n8][2], s[n8][3]));
            }
            mx0 = fmaxf(mx0, __shfl_xor_sync(0xffffffffu, mx0, 1));
            mx0 = fmaxf(mx0, __shfl_xor_sync(0xffffffffu, mx0, 2));
            mx1 = fmaxf(mx1, __shfl_xor_sync(0xffffffffu, mx1, 1));
            mx1 = fmaxf(mx1, __shfl_xor_sync(0xffffffffu, mx1, 2));
            if ((lane & 3) == 0) {
                pmax[cstrip*64 + r0] = mx0;
                pmax[cstrip*64 + r1] = mx1;
            }
        }
        __syncthreads();
        if (tid < 64) {
            float vm = fmaxf(pmax[tid], pmax[64 + tid]);
            float nm = fmaxf(m_s[tid], vm);
            al_s[tid] = __expf(m_s[tid] - nm);
            m_s[tid] = nm;
        }
        __syncthreads();
        // p = exp(s - m), store hi/lo, row sums, O rescale
        {
            float mv0 = m_s[r0], mv1 = m_s[r1];
            float a0 = al_s[r0], a1 = al_s[r1];
            float sum0 = 0.f, sum1 = 0.f;
#pragma unroll
            for (int n8 = 0; n8 < 4; n8++) {
                float p00 = __expf(s[n8][0] - mv0);
                float p01 = __expf(s[n8][1] - mv0);
                float p10 = __expf(s[n8][2] - mv1);
                float p11 = __expf(s[n8][3] - mv1);
                sum0 += p00 + p01;
                sum1 += p10 + p11;
                int c0 = cstrip*32 + n8*8 + (lane & 3)*2;
                __nv_bfloat16 h00,l00,h01,l01,h10,l10,h11,l11;
                split_bf16(p00,h00,l00); split_bf16(p01,h01,l01);
                split_bf16(p10,h10,l10); split_bf16(p11,h11,l11);
                *(__nv_bfloat162*)&PH[r0*PS + c0] = __halves2bfloat162(h00, h01);
                *(__nv_bfloat162*)&PL[r0*PS + c0] = __halves2bfloat162(l00, l01);
                *(__nv_bfloat162*)&PH[r1*PS + c0] = __halves2bfloat162(h10, h11);
                *(__nv_bfloat162*)&PL[r1*PS + c0] = __halves2bfloat162(l10, l11);
            }
            sum0 += __shfl_xor_sync(0xffffffffu, sum0, 1);
            sum0 += __shfl_xor_sync(0xffffffffu, sum0, 2);
            sum1 += __shfl_xor_sync(0xffffffffu, sum1, 1);
            sum1 += __shfl_xor_sync(0xffffffffu, sum1, 2);
            if ((lane & 3) == 0) {
                psum[cstrip*64 + r0] = sum0;
                psum[cstrip*64 + r1] = sum1;
            }
#pragma unroll
            for (int n8 = 0; n8 < 8; n8++) {
                o[n8][0] *= a0; o[n8][1] *= a0;
                o[n8][2] *= a1; o[n8][3] *= a1;
            }
        }
        __syncthreads();
        if (tid < 64) l_s[tid] = l_s[tid]*al_s[tid] + psum[tid] + psum[64 + tid];

        // O += P V  (warp tile 16 rows x 64 cols at col base cstrip*64)
#pragma unroll
        for (int ks = 0; ks < 4; ks++) {
            int kk = ks*16;
            uint32_t pHf[4], pLf[4];
            uint32_t poff = (uint32_t)(((rs + (lane & 15))*PS + kk + (lane >> 4)*8) * 2);
            ldsm_x4(pHf, ph_b + poff);
            ldsm_x4(pLf, pl_b + poff);
#pragma unroll
            for (int np = 0; np < 4; np++) {
                int n0 = cstrip*64 + np*16;
                int vrow = kk + (lane & 7) + 8*((lane >> 3) & 1);
                uint32_t voff = (uint32_t)((vrow*VS + n0 + 8*(lane >> 4)) * 2);
                uint32_t vHf[4], vLf[4];
                ldsm_x4t(vHf, vh_b + voff);
                ldsm_x4t(vLf, vl_b + voff);
                mma_bf16(o[np*2],     pHf, &vHf[0]);
                mma_bf16(o[np*2],     pHf, &vLf[0]);
                mma_bf16(o[np*2],     pLf, &vHf[0]);
                mma_bf16(o[np*2 + 1], pHf, &vHf[2]);
                mma_bf16(o[np*2 + 1], pHf, &vLf[2]);
                mma_bf16(o[np*2 + 1], pLf, &vHf[2]);
            }
        }
    } // kt

    __syncthreads();
    const float wm = tanhf(rawm[mm]) * wsc[0];
    const float inv0 = wm / l_s[r0];
    const float inv1 = wm / l_s[r1];
    float* dst = part + (size_t)mm * ((size_t)NR_ * E_);
#pragma unroll
    for (int n8 = 0; n8 < 8; n8++) {
        int col = cstrip*64 + n8*8 + (lane & 3)*2;
        *(float2*)&dst[(size_t)(rowbase + r0)*E_ + h*128 + col] =
            make_float2(o[n8][0]*inv0, o[n8][1]*inv0);
        *(float2*)&dst[(size_t)(rowbase + r1)*E_ + h*128 + col] =
            make_float2(o[n8][2]*inv1, o[n8][3]*inv1);
    }
}

// ---------------- combine 4 members + RMS norm + gamma -> bf16 hi/lo ----------------
__global__ __launch_bounds__(256) void combine_kernel(
    const float* __restrict__ part, const float* __restrict__ gamma,
    __nv_bfloat16* __restrict__ hi, __nv_bfloat16* __restrict__ lo)
{
    const int tid = threadIdx.x, lane = tid & 31, w = tid >> 5;
    const int gid = blockIdx.x * 8 + w;          // row*16 + h
    const int row = gid >> 4, h = gid & 15;
    const size_t base = (size_t)row * E_ + h*128 + lane*4;
    float4 c = make_float4(0.f, 0.f, 0.f, 0.f);
#pragma unroll
    for (int m = 0; m < 4; m++) {
        float4 p = *(const float4*)&part[(size_t)m * ((size_t)NR_ * E_) + base];
        c.x += p.x; c.y += p.y; c.z += p.z; c.w += p.w;
    }
    float ss = c.x*c.x + c.y*c.y + c.z*c.z + c.w*c.w;
#pragma unroll
    for (int off = 16; off > 0; off >>= 1)
        ss += __shfl_xor_sync(0xffffffffu, ss, off);
    const float rsc = rsqrtf(ss * (1.0f/128.0f) + 1e-5f);
    const float4 g = *(const float4*)&gamma[lane*4];
    float v0 = c.x*rsc*g.x, v1 = c.y*rsc*g.y, v2 = c.z*rsc*g.z, v3 = c.w*rsc*g.w;
    __nv_bfloat16 h0,l0,h1,l1,h2,l2,h3,l3;
    split_bf16(v0,h0,l0); split_bf16(v1,h1,l1);
    split_bf16(v2,h2,l2); split_bf16(v3,h3,l3);
    *(__nv_bfloat162*)&hi[base]   = __halves2bfloat162(h0, h1);
    *(__nv_bfloat162*)&hi[base+2] = __halves2bfloat162(h2, h3);
    *(__nv_bfloat162*)&lo[base]   = __halves2bfloat162(l0, l1);
    *(__nv_bfloat162*)&lo[base+2] = __halves2bfloat162(l2, l3);
}

// ---------------- launch ----------------
extern "C" void kernel_launch(void* const* d_in, const int* in_sizes, int n_in,
                              void* d_out, int out_size)
{
    const float* x     = (const float*)d_in[0];
    const float* cosb  = (const float*)d_in[1];
    const float* sinb  = (const float*)d_in[2];
    const float* q_w   = (const float*)d_in[3];
    const float* k_w   = (const float*)d_in[4];
    const float* v_w   = (const float*)d_in[5];
    const float* out_w = (const float*)d_in[6];
    const float* rawm  = (const float*)d_in[7];
    const float* wsc   = (const float*)d_in[8];
    const float* gamma = (const float*)d_in[9];
    float* out = (float*)d_out;

    float *gq, *gk, *gv, *gpart;
    cudaGetSymbolAddress((void**)&gq, g_q);
    cudaGetSymbolAddress((void**)&gk, g_k);
    cudaGetSymbolAddress((void**)&gv, g_v);
    cudaGetSymbolAddress((void**)&gpart, g_part);
    __nv_bfloat16 *ah, *al, *qh, *ql, *kh, *kl, *vh, *vl;
    __nv_bfloat16 *qwh, *qwl, *kwh, *kwl, *vwh, *vwl, *owh, *owl;
    cudaGetSymbolAddress((void**)&ah,  g_ah);
    cudaGetSymbolAddress((void**)&al,  g_al);
    cudaGetSymbolAddress((void**)&qh,  g_qh);
    cudaGetSymbolAddress((void**)&ql,  g_ql);
    cudaGetSymbolAddress((void**)&kh,  g_kh);
    cudaGetSymbolAddress((void**)&kl,  g_kl);
    cudaGetSymbolAddress((void**)&vh,  g_vh);
    cudaGetSymbolAddress((void**)&vl,  g_vl);
    cudaGetSymbolAddress((void**)&qwh, g_qwh);
    cudaGetSymbolAddress((void**)&qwl, g_qwl);
    cudaGetSymbolAddress((void**)&kwh, g_kwh);
    cudaGetSymbolAddress((void**)&kwl, g_kwl);
    cudaGetSymbolAddress((void**)&vwh, g_vwh);
    cudaGetSymbolAddress((void**)&vwl, g_vwl);
    cudaGetSymbolAddress((void**)&owh, g_owh);
    cudaGetSymbolAddress((void**)&owl, g_owl);

    cudaFuncSetAttribute(attn_mma, cudaFuncAttributeMaxDynamicSharedMemorySize, ATTN_SMEM);

    const float scale = 0.17677669529663687f;  // 32^-0.5

    // split conversions (fp32 -> bf16 hi/lo)
    {
        int n4;
        n4 = NR_*E_/4;   cvt_split<<<(n4+255)/256, 256>>>((const float4*)x,     (__nv_bfloat162*)ah,  (__nv_bfloat162*)al,  n4);
        n4 = E_*E_/4;    cvt_split<<<(n4+255)/256, 256>>>((const float4*)q_w,   (__nv_bfloat162*)qwh, (__nv_bfloat162*)qwl, n4);
        n4 = KVW_*E_/4;  cvt_split<<<(n4+255)/256, 256>>>((const float4*)k_w,   (__nv_bfloat162*)kwh, (__nv_bfloat162*)kwl, n4);
        n4 = KVW_*E_/4;  cvt_split<<<(n4+255)/256, 256>>>((const float4*)v_w,   (__nv_bfloat162*)vwh, (__nv_bfloat162*)vwl, n4);
        n4 = E_*E_/4;    cvt_split<<<(n4+255)/256, 256>>>((const float4*)out_w, (__nv_bfloat162*)owh, (__nv_bfloat162*)owl, n4);
    }

    // projections (HMMA bf16, split x3)
    mma_gemm<<<dim3(E_/128,   NR_/128), 256>>>(ah, al, qwh, qwl, gq, E_,   E_);
    mma_gemm<<<dim3(KVW_/128, NR_/128), 256>>>(ah, al, kwh, kwl, gk, KVW_, E_);
    mma_gemm<<<dim3(KVW_/128, NR_/128), 256>>>(ah, al, vwh, vwl, gv, KVW_, E_);

    // fused RoPE + scale + split (q), RoPE + split (k), split (v)
    rope_split<<<(NR_*64*16)/256, 256>>>(gq, cosb, sinb,
        (__nv_bfloat162*)qh, (__nv_bfloat162*)ql, 64, scale);
    rope_split<<<(NR_*16*16)/256, 256>>>(gk, cosb, sinb,
        (__nv_bfloat162*)kh, (__nv_bfloat162*)kl, 16, 1.0f);
    {
        int n4 = NR_*KVW_/4;
        cvt_split<<<(n4+255)/256, 256>>>((const float4*)gv,
            (__nv_bfloat162*)vh, (__nv_bfloat162*)vl, n4);
    }

    // attention (tensor core), one member per CTA
    attn_mma<<<dim3(T_/64, H_, B_*4), 256, ATTN_SMEM>>>(qh, ql, kh, kl, vh, vl, rawm, wsc, gpart);

    // combine + RMS norm + gamma -> bf16 split
    combine_kernel<<<NR_*16/8, 256>>>(gpart, gamma, ah, al);

    // out projection
    mma_gemm<<<dim3(E_/128, NR_/128), 256>>>(ah, al, owh, owl, out, E_, E_);
}

// round 13
// speedup vs baseline: 1.0864x; 1.0864x over previous
#include <cuda_runtime.h>
#include <cuda_bf16.h>
#include <cuda_fp16.h>
#include <math.h>
#include <stdint.h>

#define B_   2
#define T_   2048
#define E_   2048
#define H_   16
#define KVW_ 512
#define NR_  (B_*T_)   // 4096 rows

// ---------------- scratch (static device globals; no allocation) ----------------
__device__ __align__(16) float g_q[(size_t)NR_ * E_];
__device__ __align__(16) float g_k[(size_t)NR_ * KVW_];
__device__ __align__(16) float g_v[(size_t)NR_ * KVW_];
__device__ __align__(16) float g_part[4][(size_t)NR_ * E_];   // per-member w*O/l
// bf16 split buffers (GEMM path)
__device__ __align__(16) __nv_bfloat16 g_ah[(size_t)NR_ * E_];   // x, later normed
__device__ __align__(16) __nv_bfloat16 g_al[(size_t)NR_ * E_];
__device__ __align__(16) __nv_bfloat16 g_qwh[(size_t)E_ * E_];
__device__ __align__(16) __nv_bfloat16 g_qwl[(size_t)E_ * E_];
__device__ __align__(16) __nv_bfloat16 g_kwh[(size_t)KVW_ * E_];
__device__ __align__(16) __nv_bfloat16 g_kwl[(size_t)KVW_ * E_];
__device__ __align__(16) __nv_bfloat16 g_vwh[(size_t)KVW_ * E_];
__device__ __align__(16) __nv_bfloat16 g_vwl[(size_t)KVW_ * E_];
__device__ __align__(16) __nv_bfloat16 g_owh[(size_t)E_ * E_];
__device__ __align__(16) __nv_bfloat16 g_owl[(size_t)E_ * E_];
// fp16 split buffers (attention path)
__device__ __align__(16) __half g_qh[(size_t)NR_ * E_];   // roped+scaled q
__device__ __align__(16) __half g_ql[(size_t)NR_ * E_];
__device__ __align__(16) __half g_kh[(size_t)NR_ * KVW_]; // roped k
__device__ __align__(16) __half g_kl[(size_t)NR_ * KVW_];
__device__ __align__(16) __half g_vh[(size_t)NR_ * KVW_];
__device__ __align__(16) __half g_vl[(size_t)NR_ * KVW_];

__device__ __forceinline__ uint32_t smem_u32(const void* p) {
    uint32_t a;
    asm("{ .reg .u64 t; cvta.to.shared.u64 t, %1; cvt.u32.u64 %0, t; }" : "=r"(a) : "l"(p));
    return a;
}
__device__ __forceinline__ void ldsm_x4(uint32_t* r, uint32_t addr) {
    asm volatile("ldmatrix.sync.aligned.m8n8.x4.shared.b16 {%0,%1,%2,%3}, [%4];"
        : "=r"(r[0]), "=r"(r[1]), "=r"(r[2]), "=r"(r[3]) : "r"(addr));
}
__device__ __forceinline__ void ldsm_x4t(uint32_t* r, uint32_t addr) {
    asm volatile("ldmatrix.sync.aligned.m8n8.x4.trans.shared.b16 {%0,%1,%2,%3}, [%4];"
        : "=r"(r[0]), "=r"(r[1]), "=r"(r[2]), "=r"(r[3]) : "r"(addr));
}
__device__ __forceinline__ void ldsm_x2(uint32_t* r, uint32_t addr) {
    asm volatile("ldmatrix.sync.aligned.m8n8.x2.shared.b16 {%0,%1}, [%2];"
        : "=r"(r[0]), "=r"(r[1]) : "r"(addr));
}
__device__ __forceinline__ void mma_bf16(float* d, const uint32_t* a, const uint32_t* b) {
    asm volatile("mma.sync.aligned.m16n8k16.row.col.f32.bf16.bf16.f32 "
        "{%0,%1,%2,%3}, {%4,%5,%6,%7}, {%8,%9}, {%0,%1,%2,%3};"
        : "+f"(d[0]), "+f"(d[1]), "+f"(d[2]), "+f"(d[3])
        : "r"(a[0]), "r"(a[1]), "r"(a[2]), "r"(a[3]), "r"(b[0]), "r"(b[1]));
}
__device__ __forceinline__ void mma_f16(float* d, const uint32_t* a, const uint32_t* b) {
    asm volatile("mma.sync.aligned.m16n8k16.row.col.f32.f16.f16.f32 "
        "{%0,%1,%2,%3}, {%4,%5,%6,%7}, {%8,%9}, {%0,%1,%2,%3};"
        : "+f"(d[0]), "+f"(d[1]), "+f"(d[2]), "+f"(d[3])
        : "r"(a[0]), "r"(a[1]), "r"(a[2]), "r"(a[3]), "r"(b[0]), "r"(b[1]));
}
__device__ __forceinline__ void split_bf16(float v, __nv_bfloat16& h, __nv_bfloat16& l) {
    h = __float2bfloat16(v);
    l = __float2bfloat16(v - __bfloat162float(h));
}
__device__ __forceinline__ void split_f16(float v, __half& h, __half& l) {
    h = __float2half_rn(v);
    l = __float2half_rn(v - __half2float(h));
}

// ---------------- fp32 -> (bf16 hi, bf16 lo) split ----------------
__global__ void cvt_split(const float4* __restrict__ in,
                          __nv_bfloat162* __restrict__ hi,
                          __nv_bfloat162* __restrict__ lo, int n4)
{
    int i = blockIdx.x * blockDim.x + threadIdx.x;
    if (i >= n4) return;
    float4 v = in[i];
    __nv_bfloat16 h0,h1,h2,h3,l0,l1,l2,l3;
    split_bf16(v.x,h0,l0); split_bf16(v.y,h1,l1);
    split_bf16(v.z,h2,l2); split_bf16(v.w,h3,l3);
    hi[i*2]   = __halves2bfloat162(h0, h1);
    hi[i*2+1] = __halves2bfloat162(h2, h3);
    lo[i*2]   = __halves2bfloat162(l0, l1);
    lo[i*2+1] = __halves2bfloat162(l2, l3);
}

// ---------------- fp32 -> (fp16 hi, fp16 lo) split ----------------
__global__ void cvt_split_f16(const float4* __restrict__ in,
                              __half2* __restrict__ hi,
                              __half2* __restrict__ lo, int n4)
{
    int i = blockIdx.x * blockDim.x + threadIdx.x;
    if (i >= n4) return;
    float4 v = in[i];
    __half h0,h1,h2,h3,l0,l1,l2,l3;
    split_f16(v.x,h0,l0); split_f16(v.y,h1,l1);
    split_f16(v.z,h2,l2); split_f16(v.w,h3,l3);
    hi[i*2]   = __halves2half2(h0, h1);
    hi[i*2+1] = __halves2half2(h2, h3);
    lo[i*2]   = __halves2half2(l0, l1);
    lo[i*2+1] = __halves2half2(l2, l3);
}

// ---------------- fused RoPE + scale + fp16 split ----------------
__global__ void rope_split_f16(const float* __restrict__ buf,
                               const float* __restrict__ cosb,
                               const float* __restrict__ sinb,
                               __half2* __restrict__ hi,
                               __half2* __restrict__ lo,
                               int nh, float scale)
{
    int idx = blockIdx.x * blockDim.x + threadIdx.x;
    int total = NR_ * nh * 16;
    if (idx >= total) return;
    int j    = idx & 15;
    int rest = idx >> 4;
    int head = rest % nh;
    int row  = rest / nh;
    int t    = row & (T_ - 1);
    float c = cosb[t*16 + j];
    float s = sinb[t*16 + j];
    const float* p = buf + (size_t)row * (nh*32) + head*32 + 2*j;
    float x1 = p[0], x2 = p[1];
    float o1 = (x1*c - x2*s) * scale;
    float o2 = (x1*s + x2*c) * scale;
    __half h1,l1,h2,l2;
    split_f16(o1,h1,l1);
    split_f16(o2,h2,l2);
    size_t oi = ((size_t)row * (nh*32) + head*32 + 2*j) >> 1;
    hi[oi] = __halves2half2(h1, h2);
    lo[oi] = __halves2half2(l1, l2);
}

// ---------------- HMMA GEMM: C[N,J] = A[N,K] @ W[J,K]^T, split-bf16 x3 ----------------
#define TSTRIDE 40
__global__ __launch_bounds__(256) void mma_gemm(
    const __nv_bfloat16* __restrict__ Ah, const __nv_bfloat16* __restrict__ Al,
    const __nv_bfloat16* __restrict__ Bh, const __nv_bfloat16* __restrict__ Bl,
    float* __restrict__ C, int J, int K)
{
    __shared__ __align__(16) __nv_bfloat16 sm[4][128 * TSTRIDE];

    const int tid  = threadIdx.x;
    const int lane = tid & 31;
    const int warp = tid >> 5;
    const int wr   = warp >> 2;
    const int wc   = warp & 3;
    const int bm   = blockIdx.y * 128;
    const int bn   = blockIdx.x * 128;

    const uint32_t sA_h = smem_u32(sm[0]);
    const uint32_t sA_l = smem_u32(sm[1]);
    const uint32_t sB_h = smem_u32(sm[2]);
    const uint32_t sB_l = smem_u32(sm[3]);

    const int K8 = K >> 3;
    const uint4* pAh = (const uint4*)Ah;
    const uint4* pAl = (const uint4*)Al;
    const uint4* pBh = (const uint4*)Bh;
    const uint4* pBl = (const uint4*)Bl;

    float d[4][4][4];
#pragma unroll
    for (int mi = 0; mi < 4; mi++)
#pragma unroll
        for (int ni = 0; ni < 4; ni++)
#pragma unroll
            for (int e = 0; e < 4; e++) d[mi][ni][e] = 0.f;

    const int a_row = lane & 15, a_coff = (lane >> 4) * 8;
    const int b_row = lane & 7,  b_coff = ((lane >> 3) & 1) * 8;

    const int nit = K >> 5;
#pragma unroll 1
    for (int it = 0; it < nit; it++) {
        const int k0u4 = it * 4;
        __syncthreads();
#pragma unroll
        for (int u = 0; u < 2; u++) {
            int c   = u * 256 + tid;
            int row = c >> 2, ch = c & 3;
            size_t ga = (size_t)(bm + row) * K8 + k0u4 + ch;
            size_t gb = (size_t)(bn + row) * K8 + k0u4 + ch;
            *(uint4*)((char*)sm[0] + row * (TSTRIDE*2) + ch * 16) = pAh[ga];
            *(uint4*)((char*)sm[1] + row * (TSTRIDE*2) + ch * 16) = pAl[ga];
            *(uint4*)((char*)sm[2] + row * (TSTRIDE*2) + ch * 16) = pBh[gb];
            *(uint4*)((char*)sm[3] + row * (TSTRIDE*2) + ch * 16) = pBl[gb];
        }
        __syncthreads();

#pragma unroll
        for (int kk = 0; kk < 32; kk += 16) {
            uint32_t ah[4][4], al[4][4], bh[4][2], bl[4][2];
#pragma unroll
            for (int mi = 0; mi < 4; mi++) {
                int row = wr*64 + mi*16 + a_row;
                uint32_t off = (uint32_t)(row * (TSTRIDE*2) + (kk + a_coff) * 2);
                ldsm_x4(ah[mi], sA_h + off);
                ldsm_x4(al[mi], sA_l + off);
            }
#pragma unroll
            for (int ni = 0; ni < 4; ni++) {
                int row = wc*32 + ni*8 + b_row;
                uint32_t off = (uint32_t)(row * (TSTRIDE*2) + (kk + b_coff) * 2);
                ldsm_x2(bh[ni], sB_h + off);
                ldsm_x2(bl[ni], sB_l + off);
            }
#pragma unroll
            for (int mi = 0; mi < 4; mi++)
#pragma unroll
                for (int ni = 0; ni < 4; ni++) {
                    mma_bf16(d[mi][ni], ah[mi], bh[ni]);
                    mma_bf16(d[mi][ni], ah[mi], bl[ni]);
                    mma_bf16(d[mi][ni], al[mi], bh[ni]);
                }
        }
    }

#pragma unroll
    for (int mi = 0; mi < 4; mi++) {
#pragma unroll
        for (int ni = 0; ni < 4; ni++) {
            int row = bm + wr*64 + mi*16 + (lane >> 2);
            int col = bn + wc*32 + ni*8 + (lane & 3)*2;
            *(float2*)&C[(size_t)row * J + col]       = make_float2(d[mi][ni][0], d[mi][ni][1]);
            *(float2*)&C[(size_t)(row + 8) * J + col] = make_float2(d[mi][ni][2], d[mi][ni][3]);
        }
    }
}

// ---------------- HMMA flash attention (fp16, 2-term PV): one (q-tile, head, batch, member) per CTA ----------------
// smem layout (bytes): QH 0, QL 5120, KH 10240, KL 15360, VH 20480, VL 37888,
//                      PH 55296, pmax 64512, psum 65024, total 65536
#define QS 40
#define VS 136
#define PS 72
#define ATTN_SMEM 65536
__global__ __launch_bounds__(256) void attn_mma(
    const __half* __restrict__ qh, const __half* __restrict__ ql,
    const __half* __restrict__ kh, const __half* __restrict__ kl,
    const __half* __restrict__ vh, const __half* __restrict__ vl,
    const float* __restrict__ rawm, const float* __restrict__ wsc,
    float* __restrict__ part)
{
    extern __shared__ char sm[];
    __half* QH = (__half*)(sm);
    __half* QL = (__half*)(sm + 5120);
    __half* KH = (__half*)(sm + 10240);
    __half* KL = (__half*)(sm + 15360);
    __half* VH = (__half*)(sm + 20480);
    __half* VL = (__half*)(sm + 37888);
    __half* PH = (__half*)(sm + 55296);
    float* pmax = (float*)(sm + 64512);  // [2][64]
    float* psum = (float*)(sm + 65024);  // [2][64]

    const int tid    = threadIdx.x;
    const int lane   = tid & 31;
    const int warp   = tid >> 5;
    const int rs     = (warp & 3) * 16;   // row strip
    const int cstrip = warp >> 2;         // 0/1
    const int qt  = (int)gridDim.x - 1 - (int)blockIdx.x;
    const int h   = blockIdx.y;
    const int bz  = blockIdx.z;
    const int b   = bz >> 2, mm = bz & 3;
    const int hkv = h >> 2;
    const int rowbase = b*T_ + qt*64;

    const uint32_t qh_b = smem_u32(QH), ql_b = smem_u32(QL);
    const uint32_t kh_b = smem_u32(KH), kl_b = smem_u32(KL);
    const uint32_t vh_b = smem_u32(VH), vl_b = smem_u32(VL);
    const uint32_t ph_b = smem_u32(PH);

    // load Q tile (pre-roped, pre-scaled, pre-split fp16)
    {
        int r = tid >> 2, seg = tid & 3;
        size_t eo = (size_t)(rowbase + r)*E_ + (h*4 + mm)*32 + seg*8;
        *(uint4*)(QH + r*QS + seg*8) = *(const uint4*)(qh + eo);
        *(uint4*)(QL + r*QS + seg*8) = *(const uint4*)(ql + eo);
    }

    float o[8][4];
#pragma unroll
    for (int n8 = 0; n8 < 8; n8++)
#pragma unroll
        for (int e = 0; e < 4; e++) o[n8][e] = 0.f;

    const int r0 = rs + (lane >> 2);
    const int r1 = r0 + 8;
    // register-resident softmax state (per-thread rows r0/r1; l is per-cstrip half)
    float m0 = -1e30f, m1 = -1e30f, l0 = 0.f, l1 = 0.f;

#pragma unroll 1
    for (int kt = 0; kt <= qt; kt++) {
        const int kbase = b*T_ + kt*64;
        // stage K/V (fp16 pre-split)
        uint4 krh, krl, vrh[4], vrl[4];
        {
            int r = tid >> 2, seg = tid & 3;
            size_t eo = (size_t)(kbase + r)*KVW_ + (hkv*4 + mm)*32 + seg*8;
            krh = *(const uint4*)(kh + eo);
            krl = *(const uint4*)(kl + eo);
        }
#pragma unroll
        for (int u = 0; u < 4; u++) {
            int li = u*256 + tid;
            int kv = li >> 4, e8 = li & 15;
            size_t eo = (size_t)(kbase + kv)*KVW_ + hkv*128 + e8*8;
            vrh[u] = *(const uint4*)(vh + eo);
            vrl[u] = *(const uint4*)(vl + eo);
        }
        __syncthreads();   // prior iteration's MMA reads of K/V/P smem complete
        {
            int r = tid >> 2, seg = tid & 3;
            *(uint4*)(KH + r*QS + seg*8) = krh;
            *(uint4*)(KL + r*QS + seg*8) = krl;
        }
#pragma unroll
        for (int u = 0; u < 4; u++) {
            int li = u*256 + tid;
            int kv = li >> 4, e8 = li & 15;
            *(uint4*)(VH + kv*VS + e8*8) = vrh[u];
            *(uint4*)(VL + kv*VS + e8*8) = vrl[u];
        }
        __syncthreads();

        // S = Q K^T (64x64), warp tile 16x32 at (rs, cstrip*32); 3-term fp16 split
        float s[4][4];
#pragma unroll
        for (int n8 = 0; n8 < 4; n8++)
#pragma unroll
            for (int e = 0; e < 4; e++) s[n8][e] = 0.f;
#pragma unroll
        for (int ks = 0; ks < 2; ks++) {
            int kk = ks*16;
            uint32_t aH[4], aL[4];
            uint32_t aoff = (uint32_t)(((rs + (lane & 15))*QS + kk + (lane >> 4)*8) * 2);
            ldsm_x4(aH, qh_b + aoff);
            ldsm_x4(aL, ql_b + aoff);
            uint32_t bH[2][4], bL[2][4];
#pragma unroll
            for (int np = 0; np < 2; np++) {
                int nrow = cstrip*32 + np*16 + (lane & 7) + 8*(lane >> 4);
                uint32_t boff = (uint32_t)((nrow*QS + kk + 8*((lane >> 3) & 1)) * 2);
                ldsm_x4(bH[np], kh_b + boff);
                ldsm_x4(bL[np], kl_b + boff);
            }
#pragma unroll
            for (int n8 = 0; n8 < 4; n8++) {
                uint32_t* bh = &bH[n8 >> 1][(n8 & 1)*2];
                uint32_t* bl = &bL[n8 >> 1][(n8 & 1)*2];
                mma_f16(s[n8], aH, bh);
                mma_f16(s[n8], aH, bl);
                mma_f16(s[n8], aL, bh);
            }
        }
        // causal mask (diagonal tile only)
        if (kt == qt) {
#pragma unroll
            for (int n8 = 0; n8 < 4; n8++) {
                int c0 = cstrip*32 + n8*8 + (lane & 3)*2;
                if (c0     > r0) s[n8][0] = -1e30f;
                if (c0 + 1 > r0) s[n8][1] = -1e30f;
                if (c0     > r1) s[n8][2] = -1e30f;
                if (c0 + 1 > r1) s[n8][3] = -1e30f;
            }
        }
        // warp-local row max partials -> smem exchange (one sync)
        {
            float mx0 = s[0][0], mx1 = s[0][2];
#pragma unroll
            for (int n8 = 0; n8 < 4; n8++) {
                mx0 = fmaxf(mx0, fmaxf(s[n8][0], s[n8][1]));
                mx1 = fmaxf(mx1, fmaxf(s[n8][2], s[n8][3]));
            }
            mx0 = fmaxf(mx0, __shfl_xor_sync(0xffffffffu, mx0, 1));
            mx0 = fmaxf(mx0, __shfl_xor_sync(0xffffffffu, mx0, 2));
            mx1 = fmaxf(mx1, __shfl_xor_sync(0xffffffffu, mx1, 1));
            mx1 = fmaxf(mx1, __shfl_xor_sync(0xffffffffu, mx1, 2));
            if ((lane & 3) == 0) {
                pmax[cstrip*64 + r0] = mx0;
                pmax[cstrip*64 + r1] = mx1;
            }
        }
        __syncthreads();
        // every thread redundantly updates its rows' m/alpha (deterministic)
        float al0, al1;
        {
            float vm0 = fmaxf(pmax[r0], pmax[64 + r0]);
            float vm1 = fmaxf(pmax[r1], pmax[64 + r1]);
            float nm0 = fmaxf(m0, vm0);
            float nm1 = fmaxf(m1, vm1);
            al0 = __expf(m0 - nm0);
            al1 = __expf(m1 - nm1);
            m0 = nm0; m1 = nm1;
        }
        // p = exp(s - m) -> PH (fp16), own-half row sums, O rescale
        {
            float sum0 = 0.f, sum1 = 0.f;
#pragma unroll
            for (int n8 = 0; n8 < 4; n8++) {
                float p00 = __expf(s[n8][0] - m0);
                float p01 = __expf(s[n8][1] - m0);
                float p10 = __expf(s[n8][2] - m1);
                float p11 = __expf(s[n8][3] - m1);
                sum0 += p00 + p01;
                sum1 += p10 + p11;
                int c0 = cstrip*32 + n8*8 + (lane & 3)*2;
                *(__half2*)&PH[r0*PS + c0] = __floats2half2_rn(p00, p01);
                *(__half2*)&PH[r1*PS + c0] = __floats2half2_rn(p10, p11);
            }
            sum0 += __shfl_xor_sync(0xffffffffu, sum0, 1);
            sum0 += __shfl_xor_sync(0xffffffffu, sum0, 2);
            sum1 += __shfl_xor_sync(0xffffffffu, sum1, 1);
            sum1 += __shfl_xor_sync(0xffffffffu, sum1, 2);
            l0 = l0*al0 + sum0;
            l1 = l1*al1 + sum1;
#pragma unroll
            for (int n8 = 0; n8 < 8; n8++) {
                o[n8][0] *= al0; o[n8][1] *= al0;
                o[n8][2] *= al1; o[n8][3] *= al1;
            }
        }
        __syncthreads();   // PH visible to partner warp

        // O += P V  (2-term: pH*vH + pH*vL), warp tile 16 rows x 64 cols at cstrip*64
#pragma unroll
        for (int ks = 0; ks < 4; ks++) {
            int kk = ks*16;
            uint32_t pHf[4];
            uint32_t poff = (uint32_t)(((rs + (lane & 15))*PS + kk + (lane >> 4)*8) * 2);
            ldsm_x4(pHf, ph_b + poff);
#pragma unroll
            for (int np = 0; np < 4; np++) {
                int n0 = cstrip*64 + np*16;
                int vrow = kk + (lane & 7) + 8*((lane >> 3) & 1);
                uint32_t voff = (uint32_t)((vrow*VS + n0 + 8*(lane >> 4)) * 2);
                uint32_t vHf[4], vLf[4];
                ldsm_x4t(vHf, vh_b + voff);
                ldsm_x4t(vLf, vl_b + voff);
                mma_f16(o[np*2],     pHf, &vHf[0]);
                mma_f16(o[np*2],     pHf, &vLf[0]);
                mma_f16(o[np*2 + 1], pHf, &vHf[2]);
                mma_f16(o[np*2 + 1], pHf, &vLf[2]);
            }
        }
    } // kt

    // merge per-half l across the two warps sharing each row
    if ((lane & 3) == 0) {
        psum[cstrip*64 + r0] = l0;
        psum[cstrip*64 + r1] = l1;
    }
    __syncthreads();
    const float lt0 = psum[r0] + psum[64 + r0];
    const float lt1 = psum[r1] + psum[64 + r1];

    const float wm = tanhf(rawm[mm]) * wsc[0];
    const float inv0 = wm / lt0;
    const float inv1 = wm / lt1;
    float* dst = part + (size_t)mm * ((size_t)NR_ * E_);
#pragma unroll
    for (int n8 = 0; n8 < 8; n8++) {
        int col = cstrip*64 + n8*8 + (lane & 3)*2;
        *(float2*)&dst[(size_t)(rowbase + r0)*E_ + h*128 + col] =
            make_float2(o[n8][0]*inv0, o[n8][1]*inv0);
        *(float2*)&dst[(size_t)(rowbase + r1)*E_ + h*128 + col] =
            make_float2(o[n8][2]*inv1, o[n8][3]*inv1);
    }
}

// ---------------- combine 4 members + RMS norm + gamma -> bf16 hi/lo ----------------
__global__ __launch_bounds__(256) void combine_kernel(
    const float* __restrict__ part, const float* __restrict__ gamma,
    __nv_bfloat16* __restrict__ hi, __nv_bfloat16* __restrict__ lo)
{
    const int tid = threadIdx.x, lane = tid & 31, w = tid >> 5;
    const int gid = blockIdx.x * 8 + w;          // row*16 + h
    const int row = gid >> 4, h = gid & 15;
    const size_t base = (size_t)row * E_ + h*128 + lane*4;
    float4 c = make_float4(0.f, 0.f, 0.f, 0.f);
#pragma unroll
    for (int m = 0; m < 4; m++) {
        float4 p = *(const float4*)&part[(size_t)m * ((size_t)NR_ * E_) + base];
        c.x += p.x; c.y += p.y; c.z += p.z; c.w += p.w;
    }
    float ss = c.x*c.x + c.y*c.y + c.z*c.z + c.w*c.w;
#pragma unroll
    for (int off = 16; off > 0; off >>= 1)
        ss += __shfl_xor_sync(0xffffffffu, ss, off);
    const float rsc = rsqrtf(ss * (1.0f/128.0f) + 1e-5f);
    const float4 g = *(const float4*)&gamma[lane*4];
    float v0 = c.x*rsc*g.x, v1 = c.y*rsc*g.y, v2 = c.z*rsc*g.z, v3 = c.w*rsc*g.w;
    __nv_bfloat16 h0,l0,h1,l1,h2,l2,h3,l3;
    split_bf16(v0,h0,l0); split_bf16(v1,h1,l1);
    split_bf16(v2,h2,l2); split_bf16(v3,h3,l3);
    *(__nv_bfloat162*)&hi[base]   = __halves2bfloat162(h0, h1);
    *(__nv_bfloat162*)&hi[base+2] = __halves2bfloat162(h2, h3);
    *(__nv_bfloat162*)&lo[base]   = __halves2bfloat162(l0, l1);
    *(__nv_bfloat162*)&lo[base+2] = __halves2bfloat162(l2, l3);
}

// ---------------- launch ----------------
extern "C" void kernel_launch(void* const* d_in, const int* in_sizes, int n_in,
                              void* d_out, int out_size)
{
    const float* x     = (const float*)d_in[0];
    const float* cosb  = (const float*)d_in[1];
    const float* sinb  = (const float*)d_in[2];
    const float* q_w   = (const float*)d_in[3];
    const float* k_w   = (const float*)d_in[4];
    const float* v_w   = (const float*)d_in[5];
    const float* out_w = (const float*)d_in[6];
    const float* rawm  = (const float*)d_in[7];
    const float* wsc   = (const float*)d_in[8];
    const float* gamma = (const float*)d_in[9];
    float* out = (float*)d_out;

    float *gq, *gk, *gv, *gpart;
    cudaGetSymbolAddress((void**)&gq, g_q);
    cudaGetSymbolAddress((void**)&gk, g_k);
    cudaGetSymbolAddress((void**)&gv, g_v);
    cudaGetSymbolAddress((void**)&gpart, g_part);
    __nv_bfloat16 *ah, *al, *qwh, *qwl, *kwh, *kwl, *vwh, *vwl, *owh, *owl;
    __half *qh, *ql, *kh, *kl, *vh, *vl;
    cudaGetSymbolAddress((void**)&ah,  g_ah);
    cudaGetSymbolAddress((void**)&al,  g_al);
    cudaGetSymbolAddress((void**)&qh,  g_qh);
    cudaGetSymbolAddress((void**)&ql,  g_ql);
    cudaGetSymbolAddress((void**)&kh,  g_kh);
    cudaGetSymbolAddress((void**)&kl,  g_kl);
    cudaGetSymbolAddress((void**)&vh,  g_vh);
    cudaGetSymbolAddress((void**)&vl,  g_vl);
    cudaGetSymbolAddress((void**)&qwh, g_qwh);
    cudaGetSymbolAddress((void**)&qwl, g_qwl);
    cudaGetSymbolAddress((void**)&kwh, g_kwh);
    cudaGetSymbolAddress((void**)&kwl, g_kwl);
    cudaGetSymbolAddress((void**)&vwh, g_vwh);
    cudaGetSymbolAddress((void**)&vwl, g_vwl);
    cudaGetSymbolAddress((void**)&owh, g_owh);
    cudaGetSymbolAddress((void**)&owl, g_owl);

    cudaFuncSetAttribute(attn_mma, cudaFuncAttributeMaxDynamicSharedMemorySize, ATTN_SMEM);

    const float scale = 0.17677669529663687f;  // 32^-0.5

    // split conversions (fp32 -> bf16 hi/lo) for GEMM operands
    {
        int n4;
        n4 = NR_*E_/4;   cvt_split<<<(n4+255)/256, 256>>>((const float4*)x,     (__nv_bfloat162*)ah,  (__nv_bfloat162*)al,  n4);
        n4 = E_*E_/4;    cvt_split<<<(n4+255)/256, 256>>>((const float4*)q_w,   (__nv_bfloat162*)qwh, (__nv_bfloat162*)qwl, n4);
        n4 = KVW_*E_/4;  cvt_split<<<(n4+255)/256, 256>>>((const float4*)k_w,   (__nv_bfloat162*)kwh, (__nv_bfloat162*)kwl, n4);
        n4 = KVW_*E_/4;  cvt_split<<<(n4+255)/256, 256>>>((const float4*)v_w,   (__nv_bfloat162*)vwh, (__nv_bfloat162*)vwl, n4);
        n4 = E_*E_/4;    cvt_split<<<(n4+255)/256, 256>>>((const float4*)out_w, (__nv_bfloat162*)owh, (__nv_bfloat162*)owl, n4);
    }

    // projections (HMMA bf16, split x3)
    mma_gemm<<<dim3(E_/128,   NR_/128), 256>>>(ah, al, qwh, qwl, gq, E_,   E_);
    mma_gemm<<<dim3(KVW_/128, NR_/128), 256>>>(ah, al, kwh, kwl, gk, KVW_, E_);
    mma_gemm<<<dim3(KVW_/128, NR_/128), 256>>>(ah, al, vwh, vwl, gv, KVW_, E_);

    // fused RoPE + scale + fp16 split (q), RoPE + fp16 split (k), fp16 split (v)
    rope_split_f16<<<(NR_*64*16)/256, 256>>>(gq, cosb, sinb,
        (__half2*)qh, (__half2*)ql, 64, scale);
    rope_split_f16<<<(NR_*16*16)/256, 256>>>(gk, cosb, sinb,
        (__half2*)kh, (__half2*)kl, 16, 1.0f);
    {
        int n4 = NR_*KVW_/4;
        cvt_split_f16<<<(n4+255)/256, 256>>>((const float4*)gv,
            (__half2*)vh, (__half2*)vl, n4);
    }

    // attention (tensor core fp16), one member per CTA
    attn_mma<<<dim3(T_/64, H_, B_*4), 256, ATTN_SMEM>>>(qh, ql, kh, kl, vh, vl, rawm, wsc, gpart);

    // combine + RMS norm + gamma -> bf16 split
    combine_kernel<<<NR_*16/8, 256>>>(gpart, gamma, ah, al);

    // out projection
    mma_gemm<<<dim3(E_/128, NR_/128), 256>>>(ah, al, owh, owl, out, E_, E_);
}